// round 2
// baseline (speedup 1.0000x reference)
#include <cuda_runtime.h>
#include <cstdint>

// Problem constants (fixed by the dataset)
#define NMAX      50000
#define IN_FEATS  256
#define NHEADS    4
#define OUTF      64
#define HF        (NHEADS * OUTF)   // 256 = per-node projected width
#define EMAX      (NMAX * 16)       // 800000 edges
#define NEG_SLOPE 0.2f
#define MAXDEG    32                // dataset uses fixed deg=16; headroom

// ---------------------------------------------------------------------------
// Scratch (no cudaMalloc allowed)
// ---------------------------------------------------------------------------
__device__ float g_h[(size_t)NMAX * HF];        // 51.2 MB projected features
__device__ float g_attn_row[(size_t)NMAX * NHEADS];
__device__ float g_attn_col[(size_t)NMAX * NHEADS];
__device__ int   g_row_ptr[NMAX + 1];           // int32-normalized CSR
__device__ int   g_col_ind[EMAX];

// ---------------------------------------------------------------------------
// Kernel 0: normalize index arrays to int32.
// JAX without x64 silently makes "int64" arrays int32 — detect on device:
// element 1 of row_ptr is DEG(=16). Read as int32 words:
//   int32 layout -> words[1] == 16 ; int64 layout -> words[1] == 0 (high word).
// ---------------------------------------------------------------------------
__global__ void convert_idx_kernel(const void* __restrict__ row_ptr_raw,
                                   const void* __restrict__ col_ind_raw,
                                   int n_plus1, int e)
{
    const int i = blockIdx.x * blockDim.x + threadIdx.x;
    const int* rp32 = (const int*)row_ptr_raw;
    const bool is64 = (rp32[1] == 0);

    if (i < n_plus1) {
        g_row_ptr[i] = is64 ? (int)((const long long*)row_ptr_raw)[i]
                            : rp32[i];
    }
    if (i < e) {
        g_col_ind[i] = is64 ? (int)((const long long*)col_ind_raw)[i]
                            : ((const int*)col_ind_raw)[i];
    }
}

// ---------------------------------------------------------------------------
// Kernel 1: SGEMM  h[M,256] = feat[M,256] @ W[256,256]
// Classic 128x128 tile, BK=8, 256 threads, 8x8 per-thread register tile.
// ---------------------------------------------------------------------------
#define BM 128
#define BN 128
#define BK 8
#define TM 8
#define TN 8

__global__ __launch_bounds__(256) void sgemm_kernel(
    const float* __restrict__ A,   // [M, 256]
    const float* __restrict__ B,   // [256, 256]
    int M)
{
    const int K = IN_FEATS;
    const int N = HF;

    __shared__ float As[BK][BM];
    __shared__ float Bs[BK][BN];

    const int block_m = blockIdx.y * BM;
    const int block_n = blockIdx.x * BN;
    const int tid = threadIdx.x;

    const int tx = tid & 15;   // N direction (16 threads)
    const int ty = tid >> 4;   // M direction (16 threads)

    // A-tile load map: 128 rows x 8 cols = 256 float4; one float4 per thread
    const int a_row = tid >> 1;
    const int a_col = (tid & 1) * 4;
    // B-tile load map: 8 rows x 128 cols = 256 float4
    const int b_row = tid >> 5;
    const int b_col = (tid & 31) * 4;

    float acc[TM][TN];
#pragma unroll
    for (int i = 0; i < TM; i++)
#pragma unroll
        for (int j = 0; j < TN; j++) acc[i][j] = 0.0f;

    for (int k0 = 0; k0 < K; k0 += BK) {
        // Load A tile (guarded on M), store transposed As[k][m]
        float4 av = make_float4(0.f, 0.f, 0.f, 0.f);
        const int gm = block_m + a_row;
        if (gm < M)
            av = *reinterpret_cast<const float4*>(A + (size_t)gm * K + k0 + a_col);
        As[a_col + 0][a_row] = av.x;
        As[a_col + 1][a_row] = av.y;
        As[a_col + 2][a_row] = av.z;
        As[a_col + 3][a_row] = av.w;

        // Load B tile (K,N both multiples of tile — unguarded)
        const float4 bv = *reinterpret_cast<const float4*>(
            B + (size_t)(k0 + b_row) * N + block_n + b_col);
        *reinterpret_cast<float4*>(&Bs[b_row][b_col]) = bv;

        __syncthreads();

#pragma unroll
        for (int k = 0; k < BK; k++) {
            float ar[TM], br[TN];
#pragma unroll
            for (int i = 0; i < TM; i++) ar[i] = As[k][ty * TM + i];
#pragma unroll
            for (int j = 0; j < TN; j++) br[j] = Bs[k][tx * TN + j];
#pragma unroll
            for (int i = 0; i < TM; i++)
#pragma unroll
                for (int j = 0; j < TN; j++)
                    acc[i][j] = fmaf(ar[i], br[j], acc[i][j]);
        }
        __syncthreads();
    }

    // Store C tile
#pragma unroll
    for (int i = 0; i < TM; i++) {
        const int gm = block_m + ty * TM + i;
        if (gm < M) {
            float* crow = g_h + (size_t)gm * N + block_n + tx * TN;
#pragma unroll
            for (int j = 0; j < TN; j += 4) {
                float4 v = make_float4(acc[i][j], acc[i][j + 1],
                                       acc[i][j + 2], acc[i][j + 3]);
                *reinterpret_cast<float4*>(crow + j) = v;
            }
        }
    }
}

// ---------------------------------------------------------------------------
// Kernel 2: per-node attention scores
//   attn_row[n,h] = sum_f attn_l[h,f] * h[n,h,f]
//   attn_col[n,h] = sum_f attn_r[h,f] * h[n,h,f]
// One CTA (256 threads) per node; single pass over h.
// ---------------------------------------------------------------------------
__global__ __launch_bounds__(256) void attn_score_kernel(
    const float* __restrict__ attn_l,   // [256] = [H,F] flattened
    const float* __restrict__ attn_r)
{
    const int node = blockIdx.x;
    const int tid = threadIdx.x;

    const float v = g_h[(size_t)node * HF + tid];
    float pl = v * attn_l[tid];
    float pr = v * attn_r[tid];

    // warp reduce (32 lanes)
#pragma unroll
    for (int off = 16; off > 0; off >>= 1) {
        pl += __shfl_xor_sync(0xFFFFFFFFu, pl, off);
        pr += __shfl_xor_sync(0xFFFFFFFFu, pr, off);
    }

    __shared__ float sl[8], sr[8];
    const int wid = tid >> 5;
    if ((tid & 31) == 0) { sl[wid] = pl; sr[wid] = pr; }
    __syncthreads();

    // head h spans warps 2h and 2h+1 (64 lanes per head)
    if (tid < NHEADS) {
        g_attn_row[(size_t)node * NHEADS + tid] = sl[2 * tid] + sl[2 * tid + 1];
        g_attn_col[(size_t)node * NHEADS + tid] = sr[2 * tid] + sr[2 * tid + 1];
    }
}

// ---------------------------------------------------------------------------
// Kernel 3: per-destination softmax + weighted gather-aggregate.
// CSR rows are destinations -> edges of a dst are contiguous, no atomics.
// One CTA (256 threads) per destination node.
// ---------------------------------------------------------------------------
__global__ __launch_bounds__(256) void gat_agg_kernel(float* __restrict__ out)
{
    const int dst = blockIdx.x;
    const int tid = threadIdx.x;

    const int e0 = g_row_ptr[dst];
    int deg = g_row_ptr[dst + 1] - e0;
    if (deg > MAXDEG) deg = MAXDEG;   // safety clamp (dataset: deg == 16)

    __shared__ int   s_src[MAXDEG];
    __shared__ float s_alpha[MAXDEG * NHEADS];

    if (tid < deg) s_src[tid] = g_col_ind[e0 + tid];
    __syncthreads();

    // raw scores + leaky relu: one thread per (edge, head)
    if (tid < deg * NHEADS) {
        const int e = tid >> 2;
        const int h = tid & 3;
        float s = g_attn_row[(size_t)dst * NHEADS + h] +
                  g_attn_col[(size_t)s_src[e] * NHEADS + h];
        s = (s >= 0.f) ? s : NEG_SLOPE * s;
        s_alpha[e * NHEADS + h] = s;
    }
    __syncthreads();

    // softmax over the deg edges, per head (deg is tiny: serial per head)
    if (tid < NHEADS) {
        float m = -1e30f;
        for (int e = 0; e < deg; e++)
            m = fmaxf(m, s_alpha[e * NHEADS + tid]);
        float sum = 0.f;
        for (int e = 0; e < deg; e++) {
            float ex = __expf(s_alpha[e * NHEADS + tid] - m);
            s_alpha[e * NHEADS + tid] = ex;
            sum += ex;
        }
        const float inv = 1.0f / sum;
        for (int e = 0; e < deg; e++)
            s_alpha[e * NHEADS + tid] *= inv;
    }
    __syncthreads();

    // aggregate: thread tid owns output feature (h = tid/64, f = tid%64)
    const int h = tid >> 6;
    float acc = 0.f;
#pragma unroll 4
    for (int e = 0; e < deg; e++) {
        acc = fmaf(s_alpha[e * NHEADS + h],
                   __ldg(&g_h[(size_t)s_src[e] * HF + tid]), acc);
    }
    out[(size_t)dst * HF + tid] = acc;
}

// ---------------------------------------------------------------------------
// Launch
// Inputs (metadata order): row_ptr(N+1), col_ind(E), col_ptr(N+1), row_ind(E),
// feat(f32,N*256), W(f32,256*256), attn_l(f32,256), attn_r(f32,256)
// Output: f32 [N, 4, 64]
// ---------------------------------------------------------------------------
extern "C" void kernel_launch(void* const* d_in, const int* in_sizes, int n_in,
                              void* d_out, int out_size)
{
    const void*  row_ptr_raw = d_in[0];
    const void*  col_ind_raw = d_in[1];
    const float* feat   = (const float*)d_in[4];
    const float* W      = (const float*)d_in[5];
    const float* attn_l = (const float*)d_in[6];
    const float* attn_r = (const float*)d_in[7];
    float* out = (float*)d_out;

    const int n_plus1 = in_sizes[0];      // N + 1
    const int n = n_plus1 - 1;            // 50000
    int e = in_sizes[1];                  // 800000
    if (e > EMAX) e = EMAX;

    // 0) normalize indices to int32 (handles int32-or-int64 input layout)
    {
        const int total = (e > n_plus1) ? e : n_plus1;
        convert_idx_kernel<<<(total + 255) / 256, 256>>>(
            row_ptr_raw, col_ind_raw, n_plus1, e);
    }

    // 1) h = feat @ W
    dim3 ggrid(HF / BN, (n + BM - 1) / BM);
    sgemm_kernel<<<ggrid, 256>>>(feat, W, n);

    // 2) attn_row / attn_col
    attn_score_kernel<<<n, 256>>>(attn_l, attn_r);

    // 3) softmax + aggregate
    gat_agg_kernel<<<n, 256>>>(out);
}